// round 1
// baseline (speedup 1.0000x reference)
#include <cuda_runtime.h>
#include <math.h>

// Problem constants (fixed shapes from reference)
#define NB   64    // batch
#define T1   33    // text tokens incl. CLS
#define TL   32    // text latents (T1-1)
#define I1   197   // video tokens
#define CD   512   // channels
#define TEMP 0.07f

// Scratch (device globals; no allocation allowed in kernel_launch)
__device__ float g_te[NB * TL * CD];   // normalized text latents  (4.2 MB)
__device__ float g_ve[NB * I1 * CD];   // normalized video embeds (25.8 MB)
__device__ float g_tti[NB * NB];       // text_to_image[x][y]

// ---------------------------------------------------------------------------
// Kernel 1a: column norms over the T axis, write normalized latents t=1..32
// grid 64 (b), block 512 (c). Fully coalesced along c.
// ---------------------------------------------------------------------------
__global__ void knorm_text(const float* __restrict__ x) {
    int b = blockIdx.x, c = threadIdx.x;
    const float* p = x + (size_t)b * T1 * CD + c;
    float s = 0.f;
#pragma unroll
    for (int t = 0; t < T1; t++) { float v = p[t * CD]; s += v * v; }
    float inv = 1.0f / sqrtf(s);
    float* o = g_te + (size_t)b * TL * CD + c;
#pragma unroll 4
    for (int t = 0; t < TL; t++) o[t * CD] = p[(t + 1) * CD] * inv;
}

// ---------------------------------------------------------------------------
// Kernel 1b: column norms over the I axis, write normalized video embeds
// ---------------------------------------------------------------------------
__global__ void knorm_video(const float* __restrict__ x) {
    int b = blockIdx.x, c = threadIdx.x;
    const float* p = x + (size_t)b * I1 * CD + c;
    float s = 0.f;
    for (int t = 0; t < I1; t++) { float v = p[t * CD]; s += v * v; }
    float inv = 1.0f / sqrtf(s);
    float* o = g_ve + (size_t)b * I1 * CD + c;
    for (int t = 0; t < I1; t++) o[t * CD] = p[t * CD] * inv;
}

// ---------------------------------------------------------------------------
// Kernel 2: per (x,y) block — 32x197 GEMM (K=512) with running row-max over i,
// then masked mean over t. 128 threads, 8(t)x4(i) micro-tile, i-tiles of 128.
// A reads from smem are warp-uniform (broadcast): 3 LDS.128 per 32 FMAs.
// ---------------------------------------------------------------------------
#define KC    32          // k-chunk
#define ITILE 128

__global__ void __launch_bounds__(128, 4)
ksim(const int* __restrict__ amask) {
    __shared__ float As[KC][36];      // [k][t]  (pad 36: float4-aligned rows)
    __shared__ float Bs[KC][132];     // [k][i]  (pad 132)
    __shared__ float tmax[TL];

    const int x = blockIdx.x;
    const int y = blockIdx.y;
    const int tid = threadIdx.x;
    const int b = tid & 31;           // i-group: cols 4b..4b+3
    const int a = tid >> 5;           // t-group (== warp id): rows 8a..8a+7

    if (tid < TL) tmax[tid] = -3.4e38f;

    const float* Ag = g_te + (size_t)x * TL * CD;
    const float* Bg = g_ve + (size_t)y * I1 * CD;

#pragma unroll 1
    for (int it = 0; it < 2; it++) {
        const int i0 = it * ITILE;
        float acc[8][4];
#pragma unroll
        for (int r = 0; r < 8; r++)
#pragma unroll
            for (int j = 0; j < 4; j++) acc[r][j] = 0.f;

#pragma unroll 1
        for (int k0 = 0; k0 < CD; k0 += KC) {
            __syncthreads();   // previous chunk's compute done before overwrite
            // Load A chunk: 32x32 floats = 256 float4, 2 per thread, transposed
#pragma unroll
            for (int r = 0; r < 2; r++) {
                int idx = tid + 128 * r;          // 0..255
                int t = idx >> 3, c = idx & 7;
                float4 v = *(const float4*)(Ag + t * CD + k0 + 4 * c);
                As[4 * c + 0][t] = v.x; As[4 * c + 1][t] = v.y;
                As[4 * c + 2][t] = v.z; As[4 * c + 3][t] = v.w;
            }
            // Load B chunk: 128x32 floats = 1024 float4, 8 per thread, transposed
#pragma unroll
            for (int r = 0; r < 8; r++) {
                int idx = tid + 128 * r;          // 0..1023
                int ii = idx >> 3, c = idx & 7;
                int gi = i0 + ii;
                float4 v = make_float4(0.f, 0.f, 0.f, 0.f);
                if (gi < I1) v = *(const float4*)(Bg + (size_t)gi * CD + k0 + 4 * c);
                Bs[4 * c + 0][ii] = v.x; Bs[4 * c + 1][ii] = v.y;
                Bs[4 * c + 2][ii] = v.z; Bs[4 * c + 3][ii] = v.w;
            }
            __syncthreads();

#pragma unroll
            for (int kk = 0; kk < KC; kk++) {
                float4 a0 = *(const float4*)&As[kk][8 * a];
                float4 a1 = *(const float4*)&As[kk][8 * a + 4];
                float4 bv = *(const float4*)&Bs[kk][4 * b];
                float av[8] = {a0.x, a0.y, a0.z, a0.w, a1.x, a1.y, a1.z, a1.w};
                float bb[4] = {bv.x, bv.y, bv.z, bv.w};
#pragma unroll
                for (int r = 0; r < 8; r++)
#pragma unroll
                    for (int j = 0; j < 4; j++)
                        acc[r][j] += av[r] * bb[j];
            }
        }

        // Fold this i-tile into the running per-t max (mask i >= 197)
        float m[8];
#pragma unroll
        for (int r = 0; r < 8; r++) {
            float mm = -3.4e38f;
#pragma unroll
            for (int j = 0; j < 4; j++)
                if (i0 + 4 * b + j < I1) mm = fmaxf(mm, acc[r][j]);
            m[r] = mm;
        }
#pragma unroll
        for (int o = 16; o > 0; o >>= 1)
#pragma unroll
            for (int r = 0; r < 8; r++)
                m[r] = fmaxf(m[r], __shfl_xor_sync(0xffffffffu, m[r], o));
        if (b == 0) {
#pragma unroll
            for (int r = 0; r < 8; r++)
                tmax[8 * a + r] = fmaxf(tmax[8 * a + r], m[r]);
        }
        __syncthreads();
    }

    // Masked mean over t (mask row = x), temperature applied here
    if (tid < TL) {
        int mk = amask[x * T1 + 1 + tid] != 0;
        float v = mk ? tmax[tid] * TEMP : 0.f;
        float cnt = mk ? 1.f : 0.f;
#pragma unroll
        for (int o = 16; o > 0; o >>= 1) {
            v   += __shfl_xor_sync(0xffffffffu, v, o);
            cnt += __shfl_xor_sync(0xffffffffu, cnt, o);
        }
        if (tid == 0) g_tti[x * NB + y] = v / fmaxf(cnt, 1e-6f);
    }
}

// ---------------------------------------------------------------------------
// Kernel 3: contrastive loss over the 64x64 tti matrix -> scalar
// ---------------------------------------------------------------------------
__global__ void kloss(float* __restrict__ out) {
    __shared__ float sl[NB];
    int x = threadIdx.x;                 // 64 threads
    const float* row = g_tti + x * NB;
    float den = 0.f;
#pragma unroll 8
    for (int yy = 0; yy < NB; yy++) den += expf(row[yy]);
    float pos = expf(row[x]);
    sl[x] = -logf(pos / den + 1e-20f);
    __syncthreads();
    if (x == 0) {
        float s = 0.f;
#pragma unroll
        for (int i = 0; i < NB; i++) s += sl[i];
        out[0] = s * (1.0f / NB);
    }
}

// ---------------------------------------------------------------------------
extern "C" void kernel_launch(void* const* d_in, const int* in_sizes, int n_in,
                              void* d_out, int out_size) {
    const float* text  = (const float*)d_in[0];   // (64,33,512) f32
    const float* video = (const float*)d_in[1];   // (64,197,512) f32
    const int*   mask  = (const int*)d_in[2];     // (64,33) i32

    knorm_text<<<NB, CD>>>(text);
    knorm_video<<<NB, CD>>>(video);
    ksim<<<dim3(NB, NB), 128>>>(mask);
    kloss<<<1, NB>>>((float*)d_out);
}

// round 3
// speedup vs baseline: 6.9068x; 6.9068x over previous
#include <cuda_runtime.h>
#include <cuda_bf16.h>
#include <math.h>
#include <stdint.h>

// Shapes
#define NB   64
#define T1   33
#define TL   32
#define I1   197
#define IP   256      // padded i
#define CD   512
#define TEMP 0.07f

// Scratch
__device__ __align__(256) __nv_bfloat16 g_teb[NB * TL * CD];   // [x*32+t][d]
__device__ __align__(256) __nv_bfloat16 g_veb[NB * IP * CD];   // [y][i(pad)][d]
__device__ float g_tti[NB * NB];

// ---------------------------------------------------------------------------
// Portable PTX helpers (sm_80+): cp.async, ldmatrix, mma.sync bf16
// ---------------------------------------------------------------------------
__device__ __forceinline__ uint32_t smem_u32(const void* p) {
    uint32_t a;
    asm("{ .reg .u64 t; cvta.to.shared.u64 t, %1; cvt.u32.u64 %0, t; }"
        : "=r"(a) : "l"(p));
    return a;
}
#define SWZ(o) ((o) ^ ((((uint32_t)(o)) >> 3) & 0x70u))

__device__ __forceinline__ void cp16(uint32_t dst, const void* src) {
    asm volatile("cp.async.cg.shared.global [%0], [%1], 16;"
                 :: "r"(dst), "l"(src) : "memory");
}
__device__ __forceinline__ void ldm_x4(uint32_t& r0, uint32_t& r1,
                                       uint32_t& r2, uint32_t& r3, uint32_t a) {
    asm volatile("ldmatrix.sync.aligned.m8n8.x4.shared.b16 {%0,%1,%2,%3}, [%4];"
                 : "=r"(r0), "=r"(r1), "=r"(r2), "=r"(r3) : "r"(a));
}
__device__ __forceinline__ void mma16816(float* d, const uint32_t* a,
                                         uint32_t b0, uint32_t b1) {
    asm volatile(
        "mma.sync.aligned.m16n8k16.row.col.f32.bf16.bf16.f32 "
        "{%0,%1,%2,%3}, {%4,%5,%6,%7}, {%8,%9}, {%0,%1,%2,%3};"
        : "+f"(d[0]), "+f"(d[1]), "+f"(d[2]), "+f"(d[3])
        : "r"(a[0]), "r"(a[1]), "r"(a[2]), "r"(a[3]), "r"(b0), "r"(b1));
}

// ---------------------------------------------------------------------------
// Norm kernels -> bf16 operands (+ zero pad for video i=197..255)
// ---------------------------------------------------------------------------
__global__ void knorm_text(const float* __restrict__ x) {
    int b = blockIdx.x, c = threadIdx.x;     // grid 64, block 512
    const float* p = x + (size_t)b * T1 * CD + c;
    float s = 0.f;
#pragma unroll
    for (int t = 0; t < T1; t++) { float v = p[t * CD]; s += v * v; }
    float inv = 1.0f / sqrtf(s);
    __nv_bfloat16* o = g_teb + (size_t)b * TL * CD + c;
#pragma unroll 4
    for (int t = 0; t < TL; t++) o[t * CD] = __float2bfloat16(p[(t + 1) * CD] * inv);
}

__global__ void knorm_video(const float* __restrict__ x) {
    int b = blockIdx.x;                        // grid (64,4), block 128
    int c = blockIdx.y * 128 + threadIdx.x;
    const float* p = x + (size_t)b * I1 * CD + c;
    float s = 0.f;
    for (int t = 0; t < I1; t++) { float v = p[t * CD]; s += v * v; }
    float inv = 1.0f / sqrtf(s);
    __nv_bfloat16* o = g_veb + (size_t)b * IP * CD + c;
    for (int t = 0; t < I1; t++) o[t * CD] = __float2bfloat16(p[t * CD] * inv);
    __nv_bfloat16 z = __float2bfloat16(0.f);
    for (int t = I1; t < IP; t++) o[t * CD] = z;
}

// ---------------------------------------------------------------------------
// ksim: CTA (q,y): D[128,256] = A(128x512) * B(256x512)^T via mma.sync bf16.
// 512 thr = 16 warps, 4(M)x4(N); warp tile 32x64. K-chunks of 64, SW128 smem,
// double-buffered cp.async. Epilogue: in-register row-max -> masked mean.
// smem: rowmax[128][4] at 0, A bufs at 2048, B bufs after.
// ---------------------------------------------------------------------------
#define SM_RMAX  0
#define SM_A0    2048
#define SM_A1    (SM_A0 + 16384)
#define SM_B0    (SM_A1 + 16384)
#define SM_B1    (SM_B0 + 32768)
#define SM_TOTAL (SM_B1 + 32768)      // 100352 bytes

__global__ void __launch_bounds__(512, 1)
ksim(const int* __restrict__ amask) {
    extern __shared__ char smem[];
    const uint32_t sb = smem_u32(smem);
    const int tid = threadIdx.x, wid = tid >> 5, lid = tid & 31;
    const int wm = wid & 3;            // M group: rows 32*wm..+31
    const int wn = wid >> 2;           // N group: cols 64*wn..+63
    const int q = blockIdx.x, y = blockIdx.y;

    const __nv_bfloat16* Ag = g_teb + (size_t)q * 128 * CD;
    const __nv_bfloat16* Bg = g_veb + (size_t)y * IP * CD;
    const uint32_t Ab[2] = { sb + SM_A0, sb + SM_A1 };
    const uint32_t Bb[2] = { sb + SM_B0, sb + SM_B1 };

    auto load_chunk = [&](int c, int buf) {
        const int koff = c * 64;
#pragma unroll
        for (int r = 0; r < 2; r++) {                 // A: 1024 x 16B
            int idx = tid + 512 * r;
            int row = idx >> 3, seg = idx & 7;
            cp16(Ab[buf] + SWZ(row * 128 + seg * 16), Ag + row * CD + koff + seg * 8);
        }
#pragma unroll
        for (int r = 0; r < 4; r++) {                 // B: 2048 x 16B
            int idx = tid + 512 * r;
            int row = idx >> 3, seg = idx & 7;
            cp16(Bb[buf] + (row >> 7) * 16384 + SWZ((row & 127) * 128 + seg * 16),
                 Bg + (size_t)row * CD + koff + seg * 8);
        }
    };

    float acc[2][8][4];
#pragma unroll
    for (int mi = 0; mi < 2; mi++)
#pragma unroll
        for (int nj = 0; nj < 8; nj++)
#pragma unroll
            for (int d = 0; d < 4; d++) acc[mi][nj][d] = 0.f;

    load_chunk(0, 0);
    asm volatile("cp.async.commit_group;" ::: "memory");

#pragma unroll 1
    for (int c = 0; c < 8; c++) {
        if (c < 7) {
            load_chunk(c + 1, (c + 1) & 1);
            asm volatile("cp.async.commit_group;" ::: "memory");
            asm volatile("cp.async.wait_group 1;" ::: "memory");
        } else {
            asm volatile("cp.async.wait_group 0;" ::: "memory");
        }
        __syncthreads();

        const uint32_t Abase = Ab[c & 1];
        const uint32_t Bbase = Bb[c & 1];
#pragma unroll
        for (int ks = 0; ks < 4; ks++) {
            const int kb = ks * 32;                    // byte offset of k0 within 128B row
            // A frags: 2 m16 tiles
            uint32_t af[2][4];
#pragma unroll
            for (int mi = 0; mi < 2; mi++) {
                int row = 32 * wm + 16 * mi + (lid & 15);
                int col = kb + (lid >> 4) * 16;
                ldm_x4(af[mi][0], af[mi][1], af[mi][2], af[mi][3],
                       Abase + SWZ(row * 128 + col));
            }
            // B frags: 4 n16 tiles covering n64
            uint32_t bf[4][4];
#pragma unroll
            for (int ni = 0; ni < 4; ni++) {
                int row = 64 * wn + 16 * ni + (lid & 15);
                int col = kb + (lid >> 4) * 16;
                ldm_x4(bf[ni][0], bf[ni][1], bf[ni][2], bf[ni][3],
                       Bbase + (row >> 7) * 16384 + SWZ((row & 127) * 128 + col));
            }
#pragma unroll
            for (int mi = 0; mi < 2; mi++)
#pragma unroll
                for (int ni = 0; ni < 4; ni++) {
                    mma16816(acc[mi][2 * ni],     af[mi], bf[ni][0], bf[ni][2]);
                    mma16816(acc[mi][2 * ni + 1], af[mi], bf[ni][1], bf[ni][3]);
                }
        }
        __syncthreads();    // all warps done reading before next overwrite
    }

    // ---- Epilogue: per-row max over i (mask i>=197), per (row, wn) cell
    float* rowmax = (float*)(smem + SM_RMAX);          // [128][4]
#pragma unroll
    for (int mi = 0; mi < 2; mi++)
#pragma unroll
        for (int h = 0; h < 2; h++) {                  // row halves r, r+8
            float m = -3.4e38f;
#pragma unroll
            for (int nj = 0; nj < 8; nj++)
#pragma unroll
                for (int e = 0; e < 2; e++) {
                    int col = 64 * wn + 8 * nj + 2 * (lid & 3) + e;
                    float v = acc[mi][nj][2 * h + e];
                    if (col < I1) m = fmaxf(m, v);
                }
            m = fmaxf(m, __shfl_xor_sync(0xffffffffu, m, 1));
            m = fmaxf(m, __shfl_xor_sync(0xffffffffu, m, 2));
            if ((lid & 3) == 0) {
                int row = 32 * wm + 16 * mi + 8 * h + (lid >> 2);
                rowmax[4 * row + wn] = m;
            }
        }
    __syncthreads();

    if (tid < 128) {
        int row = tid;                                  // row = 32*xl + t
        float m = fmaxf(fmaxf(rowmax[4 * row], rowmax[4 * row + 1]),
                        fmaxf(rowmax[4 * row + 2], rowmax[4 * row + 3]));
        int xl = row >> 5, t = row & 31;
        int x = 4 * q + xl;
        int mk = amask[x * T1 + 1 + t] != 0;
        float v = mk ? m * TEMP : 0.f;
        float cnt = mk ? 1.f : 0.f;
#pragma unroll
        for (int o = 16; o > 0; o >>= 1) {
            v   += __shfl_xor_sync(0xffffffffu, v, o);
            cnt += __shfl_xor_sync(0xffffffffu, cnt, o);
        }
        if (t == 0) g_tti[x * NB + y] = v / fmaxf(cnt, 1e-6f);
    }
}

// ---------------------------------------------------------------------------
// kloss: 32 warps, warp w handles rows 2w, 2w+1
// ---------------------------------------------------------------------------
__global__ void kloss(float* __restrict__ out) {
    __shared__ float sl[NB];
    int w = threadIdx.x >> 5, l = threadIdx.x & 31;
#pragma unroll
    for (int rep = 0; rep < 2; rep++) {
        int x = 2 * w + rep;
        const float* row = g_tti + x * NB;
        float e = expf(row[l]) + expf(row[l + 32]);
#pragma unroll
        for (int o = 16; o > 0; o >>= 1) e += __shfl_xor_sync(0xffffffffu, e, o);
        if (l == 0) sl[x] = -logf(expf(row[x]) / e + 1e-20f);
    }
    __syncthreads();
    if (threadIdx.x < 32) {
        float s = sl[l] + sl[l + 32];
#pragma unroll
        for (int o = 16; o > 0; o >>= 1) s += __shfl_xor_sync(0xffffffffu, s, o);
        if (l == 0) out[0] = s * (1.0f / NB);
    }
}

// ---------------------------------------------------------------------------
extern "C" void kernel_launch(void* const* d_in, const int* in_sizes, int n_in,
                              void* d_out, int out_size) {
    const float* text  = (const float*)d_in[0];
    const float* video = (const float*)d_in[1];
    const int*   mask  = (const int*)d_in[2];

    static int smem_set = 0;
    if (!smem_set) {
        cudaFuncSetAttribute(ksim, cudaFuncAttributeMaxDynamicSharedMemorySize, SM_TOTAL);
        smem_set = 1;
    }

    knorm_text<<<NB, CD>>>(text);
    knorm_video<<<dim3(NB, 4), 128>>>(video);
    ksim<<<dim3(16, NB), 512, SM_TOTAL>>>(mask);
    kloss<<<1, 1024>>>((float*)d_out);
}

// round 4
// speedup vs baseline: 7.8730x; 1.1399x over previous
#include <cuda_runtime.h>
#include <cuda_bf16.h>
#include <math.h>
#include <stdint.h>

// Shapes
#define NB   64
#define T1   33
#define TL   32
#define I1   197
#define IP   256      // padded i
#define CD   512
#define TEMP 0.07f
#define NCH  8        // K chunks of 64
#define A_CH 16384    // bytes per A chunk image (128 rows x 128B)
#define B_CH 32768    // bytes per B chunk image (256 rows x 128B)

// Scratch: pre-swizzled, chunk-major SMEM images
__device__ __align__(256) __nv_bfloat16 g_Asw[16 * NCH * A_CH / 2];   //  2 MB
__device__ __align__(256) __nv_bfloat16 g_Bsw[NB * NCH * B_CH / 2];   // 16 MB
__device__ float g_tti[NB * NB];

// ---------------------------------------------------------------------------
// Portable PTX helpers (sm_90-base): cp.async.bulk, mbarrier, ldmatrix, mma
// ---------------------------------------------------------------------------
__device__ __forceinline__ uint32_t smem_u32(const void* p) {
    uint32_t a;
    asm("{ .reg .u64 t; cvta.to.shared.u64 t, %1; cvt.u32.u64 %0, t; }"
        : "=r"(a) : "l"(p));
    return a;
}
#define SWZ(o) ((o) ^ ((((uint32_t)(o)) >> 3) & 0x70u))

__device__ __forceinline__ void bulk_ld(uint32_t dst, const void* src,
                                        uint32_t bytes, uint32_t mbar) {
    asm volatile(
        "cp.async.bulk.shared::cluster.global.mbarrier::complete_tx::bytes "
        "[%0], [%1], %2, [%3];"
        :: "r"(dst), "l"(src), "r"(bytes), "r"(mbar) : "memory");
}
__device__ __forceinline__ void mbar_init(uint32_t m, uint32_t cnt) {
    asm volatile("mbarrier.init.shared.b64 [%0], %1;" :: "r"(m), "r"(cnt) : "memory");
}
__device__ __forceinline__ void mbar_expect(uint32_t m, uint32_t bytes) {
    asm volatile("mbarrier.arrive.expect_tx.shared.b64 _, [%0], %1;"
                 :: "r"(m), "r"(bytes) : "memory");
}
#define MBAR_WAIT(addr, par) do {                                               \
    uint32_t _m = (addr), _p = (par), _d;                                       \
    asm volatile("{\n\t.reg .pred p;\n\t"                                       \
        "mbarrier.try_wait.parity.acquire.cta.shared::cta.b64 p, [%1], %2;\n\t" \
        "selp.b32 %0, 1, 0, p;\n\t}" : "=r"(_d) : "r"(_m), "r"(_p) : "memory"); \
    if (!_d) {                                                                  \
        asm volatile("{\n\t.reg .pred P1;\n\tWL_%=:\n\t"                        \
            "mbarrier.try_wait.parity.acquire.cta.shared::cta.b64 P1, [%0], %1, 0x989680;\n\t" \
            "@P1 bra.uni WD_%=;\n\tbra.uni WL_%=;\n\tWD_%=:\n\t}"               \
            :: "r"(_m), "r"(_p) : "memory");                                    \
    }                                                                           \
} while (0)

__device__ __forceinline__ void ldm_x4(uint32_t& r0, uint32_t& r1,
                                       uint32_t& r2, uint32_t& r3, uint32_t a) {
    asm volatile("ldmatrix.sync.aligned.m8n8.x4.shared.b16 {%0,%1,%2,%3}, [%4];"
                 : "=r"(r0), "=r"(r1), "=r"(r2), "=r"(r3) : "r"(a));
}
__device__ __forceinline__ void mma16816(float* d, const uint32_t* a,
                                         uint32_t b0, uint32_t b1) {
    asm volatile(
        "mma.sync.aligned.m16n8k16.row.col.f32.bf16.bf16.f32 "
        "{%0,%1,%2,%3}, {%4,%5,%6,%7}, {%8,%9}, {%0,%1,%2,%3};"
        : "+f"(d[0]), "+f"(d[1]), "+f"(d[2]), "+f"(d[3])
        : "r"(a[0]), "r"(a[1]), "r"(a[2]), "r"(a[3]), "r"(b0), "r"(b1));
}

// ---------------------------------------------------------------------------
// Norm kernels -> bf16, written directly in swizzled chunk-major SMEM image
// A image (per q, per chunk): row = (x&3)*32 + t, byte (d&63)*2, SW128
// ---------------------------------------------------------------------------
__global__ void knorm_text(const float* __restrict__ x) {
    int b = blockIdx.x, d = threadIdx.x;     // grid 64, block 512
    const float* p = x + (size_t)b * T1 * CD + d;
    float s = 0.f;
#pragma unroll
    for (int t = 0; t < T1; t++) { float v = p[t * CD]; s += v * v; }
    float inv = 1.0f / sqrtf(s);
    int q = b >> 2;
    char* base = (char*)g_Asw + ((size_t)q * NCH + (d >> 6)) * A_CH;
    uint32_t colb = (d & 63) * 2;
#pragma unroll 4
    for (int t = 0; t < TL; t++) {
        int row = (b & 3) * 32 + t;
        *(__nv_bfloat16*)(base + SWZ(row * 128 + colb)) =
            __float2bfloat16(p[(t + 1) * CD] * inv);
    }
}

__global__ void knorm_video(const float* __restrict__ x) {
    int b = blockIdx.x;                        // grid (64,4), block 128
    int d = blockIdx.y * 128 + threadIdx.x;
    const float* p = x + (size_t)b * I1 * CD + d;
    float s = 0.f;
    for (int t = 0; t < I1; t++) { float v = p[t * CD]; s += v * v; }
    float inv = 1.0f / sqrtf(s);
    char* base = (char*)g_Bsw + ((size_t)b * NCH + (d >> 6)) * B_CH;
    uint32_t colb = (d & 63) * 2;
    for (int t = 0; t < I1; t++)
        *(__nv_bfloat16*)(base + SWZ(t * 128 + colb)) = __float2bfloat16(p[t * CD] * inv);
    __nv_bfloat16 z = __float2bfloat16(0.f);
    for (int t = I1; t < IP; t++)
        *(__nv_bfloat16*)(base + SWZ(t * 128 + colb)) = z;
}

// ---------------------------------------------------------------------------
// ksim: CTA (q,y): D[128,256] = A(128x512)*B(256x512)^T. 16 warps 4(M)x4(N),
// warp tile 32x64. 4-stage cp.async.bulk ring (2 bulk ops per chunk),
// mbarrier complete_tx, 1 __syncthreads per chunk. Fused max/mean epilogue.
// ---------------------------------------------------------------------------
#define SM_RMAX  0
#define SM_MB    2048
#define SM_STG   4096
#define STG_SZ   (A_CH + B_CH)              // 49152
#define SM_TOTAL (SM_STG + 4 * STG_SZ)      // 200704

__global__ void __launch_bounds__(512, 1)
ksim(const int* __restrict__ amask) {
    extern __shared__ char smem[];
    const uint32_t sb = smem_u32(smem);
    const int tid = threadIdx.x, wid = tid >> 5, lid = tid & 31;
    const int wm = wid & 3, wn = wid >> 2;
    const int q = blockIdx.x, y = blockIdx.y;

    const char* Asrc = (const char*)g_Asw + (size_t)q * NCH * A_CH;
    const char* Bsrc = (const char*)g_Bsw + (size_t)y * NCH * B_CH;

    if (tid == 0) {
#pragma unroll
        for (int s = 0; s < 4; s++) mbar_init(sb + SM_MB + 8 * s, 1);
    }
    __syncthreads();
    if (tid == 0) {
#pragma unroll
        for (int s = 0; s < 4; s++) {                 // prologue: chunks 0..3
            uint32_t mb = sb + SM_MB + 8 * s;
            uint32_t st = sb + SM_STG + s * STG_SZ;
            mbar_expect(mb, STG_SZ);
            bulk_ld(st,        Asrc + (size_t)s * A_CH, A_CH, mb);
            bulk_ld(st + A_CH, Bsrc + (size_t)s * B_CH, B_CH, mb);
        }
    }

    float acc[2][8][4];
#pragma unroll
    for (int mi = 0; mi < 2; mi++)
#pragma unroll
        for (int nj = 0; nj < 8; nj++)
#pragma unroll
            for (int d = 0; d < 4; d++) acc[mi][nj][d] = 0.f;

#pragma unroll 1
    for (int c = 0; c < NCH; c++) {
        const int s = c & 3;
        MBAR_WAIT(sb + SM_MB + 8 * s, (c >> 2) & 1);
        const uint32_t Abase = sb + SM_STG + s * STG_SZ;
        const uint32_t Bbase = Abase + A_CH;

#pragma unroll
        for (int ks = 0; ks < 4; ks++) {
            const int kb = ks * 32;
            uint32_t af[2][4];
#pragma unroll
            for (int mi = 0; mi < 2; mi++) {
                int row = 32 * wm + 16 * mi + (lid & 15);
                int col = kb + (lid >> 4) * 16;
                ldm_x4(af[mi][0], af[mi][1], af[mi][2], af[mi][3],
                       Abase + SWZ(row * 128 + col));
            }
            uint32_t bf[4][4];
#pragma unroll
            for (int ni = 0; ni < 4; ni++) {
                int row = 64 * wn + 16 * ni + (lid & 15);
                int col = kb + (lid >> 4) * 16;
                ldm_x4(bf[ni][0], bf[ni][1], bf[ni][2], bf[ni][3],
                       Bbase + SWZ(row * 128 + col));
            }
#pragma unroll
            for (int mi = 0; mi < 2; mi++)
#pragma unroll
                for (int ni = 0; ni < 4; ni++) {
                    mma16816(acc[mi][2 * ni],     af[mi], bf[ni][0], bf[ni][2]);
                    mma16816(acc[mi][2 * ni + 1], af[mi], bf[ni][1], bf[ni][3]);
                }
        }
        __syncthreads();                               // all warps done with stage s
        if (tid == 0 && c + 4 < NCH) {                 // refill stage s with chunk c+4
            uint32_t mb = sb + SM_MB + 8 * s;
            uint32_t st = Abase;
            mbar_expect(mb, STG_SZ);
            bulk_ld(st,        Asrc + (size_t)(c + 4) * A_CH, A_CH, mb);
            bulk_ld(st + A_CH, Bsrc + (size_t)(c + 4) * B_CH, B_CH, mb);
        }
    }

    // ---- Epilogue: per-row max over i (mask i>=197) -> masked mean over t
    float* rowmax = (float*)(smem + SM_RMAX);          // [128][4]
#pragma unroll
    for (int mi = 0; mi < 2; mi++)
#pragma unroll
        for (int h = 0; h < 2; h++) {
            float m = -3.4e38f;
#pragma unroll
            for (int nj = 0; nj < 8; nj++)
#pragma unroll
                for (int e = 0; e < 2; e++) {
                    int col = 64 * wn + 8 * nj + 2 * (lid & 3) + e;
                    float v = acc[mi][nj][2 * h + e];
                    if (col < I1) m = fmaxf(m, v);
                }
            m = fmaxf(m, __shfl_xor_sync(0xffffffffu, m, 1));
            m = fmaxf(m, __shfl_xor_sync(0xffffffffu, m, 2));
            if ((lid & 3) == 0) {
                int row = 32 * wm + 16 * mi + 8 * h + (lid >> 2);
                rowmax[4 * row + wn] = m;
            }
        }
    __syncthreads();

    if (tid < 128) {
        int row = tid;
        float m = fmaxf(fmaxf(rowmax[4 * row], rowmax[4 * row + 1]),
                        fmaxf(rowmax[4 * row + 2], rowmax[4 * row + 3]));
        int xl = row >> 5, t = row & 31;
        int x = 4 * q + xl;
        int mk = amask[x * T1 + 1 + t] != 0;
        float v = mk ? m * TEMP : 0.f;
        float cnt = mk ? 1.f : 0.f;
#pragma unroll
        for (int o = 16; o > 0; o >>= 1) {
            v   += __shfl_xor_sync(0xffffffffu, v, o);
            cnt += __shfl_xor_sync(0xffffffffu, cnt, o);
        }
        if (t == 0) g_tti[x * NB + y] = v / fmaxf(cnt, 1e-6f);
    }
}

// ---------------------------------------------------------------------------
// kloss: 32 warps, warp w handles rows 2w, 2w+1
// ---------------------------------------------------------------------------
__global__ void kloss(float* __restrict__ out) {
    __shared__ float sl[NB];
    int w = threadIdx.x >> 5, l = threadIdx.x & 31;
#pragma unroll
    for (int rep = 0; rep < 2; rep++) {
        int x = 2 * w + rep;
        const float* row = g_tti + x * NB;
        float e = expf(row[l]) + expf(row[l + 32]);
#pragma unroll
        for (int o = 16; o > 0; o >>= 1) e += __shfl_xor_sync(0xffffffffu, e, o);
        if (l == 0) sl[x] = -logf(expf(row[x]) / e + 1e-20f);
    }
    __syncthreads();
    if (threadIdx.x < 32) {
        float s = sl[l] + sl[l + 32];
#pragma unroll
        for (int o = 16; o > 0; o >>= 1) s += __shfl_xor_sync(0xffffffffu, s, o);
        if (l == 0) out[0] = s * (1.0f / NB);
    }
}

// ---------------------------------------------------------------------------
extern "C" void kernel_launch(void* const* d_in, const int* in_sizes, int n_in,
                              void* d_out, int out_size) {
    const float* text  = (const float*)d_in[0];
    const float* video = (const float*)d_in[1];
    const int*   mask  = (const int*)d_in[2];

    static int smem_set = 0;
    if (!smem_set) {
        cudaFuncSetAttribute(ksim, cudaFuncAttributeMaxDynamicSharedMemorySize, SM_TOTAL);
        smem_set = 1;
    }

    knorm_text<<<NB, CD>>>(text);
    knorm_video<<<dim3(NB, 4), 128>>>(video);
    ksim<<<dim3(16, NB), 512, SM_TOTAL>>>(mask);
    kloss<<<1, 1024>>>((float*)d_out);
}